// round 1
// baseline (speedup 1.0000x reference)
#include <cuda_runtime.h>
#include <stdint.h>

// Problem constants (fixed shapes from reference setup_inputs)
#define BQ 2
#define NQ 16384
#define SQ 4096
#define CQ 64
#define NS 32
#define OUTC 67            // 3 xyz + 64 feature channels
#define WARPS 4            // warps per block in main kernel

// Scratch (device globals: no allocation allowed)
__device__ float4 g_xyzp[BQ * NQ];                 // packed xyz, 512 KB
__device__ float  g_featT[(size_t)BQ * NQ * CQ];   // features transposed to [B,N,C], 8 MB

// ---------------------------------------------------------------------------
// Prep 1: pack xyz [B,N,3] -> float4 [B,N]
// ---------------------------------------------------------------------------
__global__ void pack_xyz_kernel(const float* __restrict__ xyz) {
    int i = blockIdx.x * blockDim.x + threadIdx.x;
    if (i < BQ * NQ) {
        float x = xyz[3 * i + 0];
        float y = xyz[3 * i + 1];
        float z = xyz[3 * i + 2];
        g_xyzp[i] = make_float4(x, y, z, 0.0f);
    }
}

// ---------------------------------------------------------------------------
// Prep 2: transpose features [B,C,N] -> [B,N,C]
// ---------------------------------------------------------------------------
__global__ void transpose_feat_kernel(const float* __restrict__ feat) {
    __shared__ float tile[32][33];
    int n0 = blockIdx.x * 32;
    int c0 = blockIdx.y * 32;
    int b  = blockIdx.z;
    int tx = threadIdx.x;   // 0..31
    int ty = threadIdx.y;   // 0..7

#pragma unroll
    for (int j = 0; j < 32; j += 8) {
        // read feat[b][c0+ty+j][n0+tx]  (coalesced over tx)
        tile[ty + j][tx] = feat[((size_t)b * CQ + (c0 + ty + j)) * NQ + (n0 + tx)];
    }
    __syncthreads();
#pragma unroll
    for (int j = 0; j < 32; j += 8) {
        // write featT[b][n0+ty+j][c0+tx]  (coalesced over tx)
        g_featT[((size_t)b * NQ + (n0 + ty + j)) * CQ + (c0 + tx)] = tile[tx][ty + j];
    }
}

// ---------------------------------------------------------------------------
// Main: ball query + group, one warp per center
// ---------------------------------------------------------------------------
__global__ __launch_bounds__(WARPS * 32)
void query_group_kernel(const float* __restrict__ new_xyz,
                        float* __restrict__ out) {
    __shared__ int   sh_idx[WARPS][NS];
    __shared__ float sh_feat[WARPS][NS * 65];  // pitch 65 -> conflict-free transpose

    const int warp   = threadIdx.x >> 5;
    const int lane   = threadIdx.x & 31;
    const int center = blockIdx.x * WARPS + warp;     // 0 .. B*S-1
    const int b = center / SQ;
    const int s = center % SQ;

    const float cx = new_xyz[3 * center + 0];
    const float cy = new_xyz[3 * center + 1];
    const float cz = new_xyz[3 * center + 2];

    const float4* __restrict__ xp = g_xyzp + (size_t)b * NQ;
    const float r2 = 0.1f * 0.1f;   // matches float(0.1)^2 rounding in reference

    // ---- ball query: first NS indices (ascending) with d2 < r2 ----
    int cnt = 0;
    for (int base = 0; base < NQ; base += 32) {
        float4 p = xp[base + lane];
        float dx = __fadd_rn(cx, -p.x);
        float dy = __fadd_rn(cy, -p.y);
        float dz = __fadd_rn(cz, -p.z);
        // exact reference order: (dx*dx + dy*dy) + dz*dz, no FMA contraction
        float d2 = __fadd_rn(__fadd_rn(__fmul_rn(dx, dx), __fmul_rn(dy, dy)),
                             __fmul_rn(dz, dz));
        bool hit = d2 < r2;
        unsigned m = __ballot_sync(0xffffffffu, hit);
        if (hit) {
            int slot = cnt + __popc(m & ((1u << lane) - 1u));
            if (slot < NS) sh_idx[warp][slot] = base + lane;
        }
        cnt += __popc(m);
        if (cnt >= NS) break;   // uniform across warp (ballot-derived)
    }
    __syncwarp();

    // lane k owns sample k; pad with first hit, or 0 if none
    int myidx;
    if (cnt == 0) {
        myidx = 0;
    } else {
        myidx = sh_idx[warp][(lane < cnt) ? lane : 0];
    }

    // ---- grouped_xyz channels (0..2): xyz[idx] - center, lane = sample ----
    float4 p = xp[myidx];
    float gx = __fadd_rn(p.x, -cx);
    float gy = __fadd_rn(p.y, -cy);
    float gz = __fadd_rn(p.z, -cz);

    // out[b][c][s][k] ; k = lane -> coalesced stores
    const size_t chan_stride = (size_t)SQ * NS;
    float* ob = out + ((size_t)b * OUTC * SQ + s) * NS + lane;
    ob[0 * chan_stride] = gx;
    ob[1 * chan_stride] = gy;
    ob[2 * chan_stride] = gz;

    // ---- stage 32x64 feature block through smem (coalesced global reads) ----
    const float* __restrict__ ft = g_featT + (size_t)b * NQ * CQ;
#pragma unroll 4
    for (int k = 0; k < NS; k++) {
        int row = __shfl_sync(0xffffffffu, myidx, k);
        const float* fr = ft + (size_t)row * CQ;
        sh_feat[warp][k * 65 + lane]      = fr[lane];
        sh_feat[warp][k * 65 + 32 + lane] = fr[lane + 32];
    }
    __syncwarp();

    // ---- write feature channels (3..66): lane = sample k -> coalesced ----
    float* oc = ob + 3 * chan_stride;
#pragma unroll
    for (int c = 0; c < CQ; c++) {
        oc[(size_t)c * chan_stride] = sh_feat[warp][lane * 65 + c];
    }
}

// ---------------------------------------------------------------------------
// Launch
// ---------------------------------------------------------------------------
extern "C" void kernel_launch(void* const* d_in, const int* in_sizes, int n_in,
                              void* d_out, int out_size) {
    const float* xyz     = (const float*)d_in[0];   // [B,N,3]
    const float* new_xyz = (const float*)d_in[1];   // [B,S,3]
    const float* feat    = (const float*)d_in[2];   // [B,C,N]
    float* out = (float*)d_out;                     // [B,67,S,NS]

    // prep
    {
        int total = BQ * NQ;
        pack_xyz_kernel<<<(total + 255) / 256, 256>>>(xyz);
    }
    {
        dim3 grid(NQ / 32, CQ / 32, BQ);
        dim3 block(32, 8);
        transpose_feat_kernel<<<grid, block>>>(feat);
    }
    // main
    {
        int centers = BQ * SQ;
        query_group_kernel<<<centers / WARPS, WARPS * 32>>>(new_xyz, out);
    }
}

// round 2
// speedup vs baseline: 2.3224x; 2.3224x over previous
#include <cuda_runtime.h>
#include <stdint.h>

// Fixed problem shapes
#define BQ 2
#define NQ 16384
#define SQ 4096
#define CQ 64
#define NS 32
#define OUTC 67              // 3 xyz + 64 feature channels

#define WARPS_A 16           // centers per scan block (512 threads)
#define TILE    2048         // xyz points staged per smem tile (32 KB)

// Device scratch (no allocations allowed)
__device__ float4 g_xyzp[BQ * NQ];                  // packed xyz, 512 KB (L2-resident)
__device__ float  g_featT[(size_t)BQ * NQ * CQ];    // features [B,N,C], 8 MB (L2-resident)
__device__ int    g_idx[BQ * SQ * NS];              // final sample indices, 1 MB

// ---------------------------------------------------------------------------
// Prep 1: pack xyz [B,N,3] -> float4
// ---------------------------------------------------------------------------
__global__ void pack_xyz_kernel(const float* __restrict__ xyz) {
    int i = blockIdx.x * blockDim.x + threadIdx.x;
    if (i < BQ * NQ) {
        g_xyzp[i] = make_float4(xyz[3 * i + 0], xyz[3 * i + 1], xyz[3 * i + 2], 0.0f);
    }
}

// ---------------------------------------------------------------------------
// Prep 2: transpose features [B,C,N] -> [B,N,C]
// ---------------------------------------------------------------------------
__global__ void transpose_feat_kernel(const float* __restrict__ feat) {
    __shared__ float tile[32][33];
    int n0 = blockIdx.x * 32;
    int c0 = blockIdx.y * 32;
    int b  = blockIdx.z;
    int tx = threadIdx.x;
    int ty = threadIdx.y;

#pragma unroll
    for (int j = 0; j < 32; j += 8)
        tile[ty + j][tx] = feat[((size_t)b * CQ + (c0 + ty + j)) * NQ + (n0 + tx)];
    __syncthreads();
#pragma unroll
    for (int j = 0; j < 32; j += 8)
        g_featT[((size_t)b * NQ + (n0 + ty + j)) * CQ + (c0 + tx)] = tile[tx][ty + j];
}

// ---------------------------------------------------------------------------
// Kernel A: ball query with block-cooperative smem tiling of xyz.
// One warp per center; 16 centers per block share each 32 KB xyz tile.
// Writes final (padded) indices to g_idx and the 3 grouped_xyz channels.
// ---------------------------------------------------------------------------
__global__ __launch_bounds__(WARPS_A * 32)
void ball_query_kernel(const float* __restrict__ new_xyz,
                       float* __restrict__ out) {
    __shared__ float4 tile[TILE];
    __shared__ int    sh_idx[WARPS_A][NS];
    __shared__ int    ndone;

    const int tid  = threadIdx.x;
    const int warp = tid >> 5;
    const int lane = tid & 31;
    const int center = blockIdx.x * WARPS_A + warp;   // 0 .. B*S-1
    const int bblk = (blockIdx.x * WARPS_A) / SQ;     // uniform per block (4096 % 16 == 0)
    const int s = center % SQ;

    const float cx = new_xyz[3 * center + 0];
    const float cy = new_xyz[3 * center + 1];
    const float cz = new_xyz[3 * center + 2];

    const float4* __restrict__ xp = g_xyzp + (size_t)bblk * NQ;
    const float r2 = (float)(0.1 * 0.1);   // exact reference threshold (f64 product -> f32)

    if (tid == 0) ndone = 0;

    int  cnt  = 0;
    bool done = false;

    for (int base = 0; base < NQ; base += TILE) {
        // cooperative tile load (guarded by trailing __syncthreads of prev iter)
#pragma unroll
        for (int i = tid; i < TILE; i += WARPS_A * 32)
            tile[i] = xp[base + i];
        __syncthreads();

        if (!done) {
            for (int off = 0; off < TILE; off += 32) {
                float4 p = tile[off + lane];
                float dx = __fadd_rn(cx, -p.x);
                float dy = __fadd_rn(cy, -p.y);
                float dz = __fadd_rn(cz, -p.z);
                float d2 = __fadd_rn(__fadd_rn(__fmul_rn(dx, dx), __fmul_rn(dy, dy)),
                                     __fmul_rn(dz, dz));
                bool hit = d2 < r2;
                unsigned m = __ballot_sync(0xffffffffu, hit);
                if (hit) {
                    int slot = cnt + __popc(m & ((1u << lane) - 1u));
                    if (slot < NS) sh_idx[warp][slot] = base + off + lane;
                }
                cnt += __popc(m);
                if (cnt >= NS) {                      // warp-uniform
                    done = true;
                    if (lane == 0) atomicAdd(&ndone, 1);
                    break;
                }
            }
        }
        __syncthreads();
        if (ndone == WARPS_A) break;                  // block-level early exit
    }
    __syncwarp();

    // lane k owns sample k; pad with first hit, or 0 if no hits
    int myidx = (cnt == 0) ? 0 : sh_idx[warp][(lane < cnt) ? lane : 0];
    g_idx[center * NS + lane] = myidx;

    // grouped_xyz (channels 0..2): xyz[idx] - center, coalesced over lane=k
    float4 p = g_xyzp[(size_t)bblk * NQ + myidx];
    const size_t chan_stride = (size_t)SQ * NS;
    float* ob = out + ((size_t)bblk * OUTC * SQ + s) * NS + lane;
    ob[0 * chan_stride] = __fadd_rn(p.x, -cx);
    ob[1 * chan_stride] = __fadd_rn(p.y, -cy);
    ob[2 * chan_stride] = __fadd_rn(p.z, -cz);
}

// ---------------------------------------------------------------------------
// Kernel B: feature grouping. One 128-thread block per center.
// Gathers 32 rows of [B,N,C] features (coalesced 256 B rows), transposes via
// padded smem, writes channels 3..66 coalesced over the sample dim.
// ---------------------------------------------------------------------------
__global__ __launch_bounds__(128)
void group_feat_kernel(float* __restrict__ out) {
    __shared__ float sf[NS][CQ + 1];   // pitch 65 -> conflict-free
    __shared__ int   sidx[NS];

    const int center = blockIdx.x;
    const int b = center / SQ;
    const int s = center % SQ;
    const int tid = threadIdx.x;

    if (tid < NS) sidx[tid] = g_idx[center * NS + tid];
    __syncthreads();

    // load: 2 rows per step; threads 0..63 -> row r0, 64..127 -> row r0+1
    const int half = tid >> 6;
    const int c    = tid & 63;
    const float* __restrict__ ft = g_featT + (size_t)b * NQ * CQ;
#pragma unroll
    for (int r0 = 0; r0 < NS; r0 += 2) {
        int r = r0 + half;
        sf[r][c] = ft[(size_t)sidx[r] * CQ + c];
    }
    __syncthreads();

    // write: lane=k (coalesced), 4 channels in flight per step
    const int k = tid & 31;
    const size_t chan_stride = (size_t)SQ * NS;
    float* ob = out + ((size_t)b * OUTC * SQ + s) * NS + k + 3 * chan_stride;
#pragma unroll
    for (int c0 = tid >> 5; c0 < CQ; c0 += 4) {
        ob[(size_t)c0 * chan_stride] = sf[k][c0];
    }
}

// ---------------------------------------------------------------------------
// Launch
// ---------------------------------------------------------------------------
extern "C" void kernel_launch(void* const* d_in, const int* in_sizes, int n_in,
                              void* d_out, int out_size) {
    const float* xyz     = (const float*)d_in[0];   // [B,N,3]
    const float* new_xyz = (const float*)d_in[1];   // [B,S,3]
    const float* feat    = (const float*)d_in[2];   // [B,C,N]
    float* out = (float*)d_out;                     // [B,67,S,NS]

    pack_xyz_kernel<<<(BQ * NQ + 255) / 256, 256>>>(xyz);

    {
        dim3 grid(NQ / 32, CQ / 32, BQ);
        dim3 block(32, 8);
        transpose_feat_kernel<<<grid, block>>>(feat);
    }

    ball_query_kernel<<<(BQ * SQ) / WARPS_A, WARPS_A * 32>>>(new_xyz, out);

    group_feat_kernel<<<BQ * SQ, 128>>>(out);
}

// round 3
// speedup vs baseline: 6.0584x; 2.6087x over previous
#include <cuda_runtime.h>
#include <stdint.h>

// Fixed problem shapes
#define BQ 2
#define NQ 16384
#define SQ 4096
#define CQ 64
#define NS 32
#define OUTC 67
#define NCELL 1000           // 10x10x10 grid, cell = radius = 0.1
#define WARPS_B 8            // centers per ball-query block

// Device scratch (zero-initialized at module load; no allocations allowed)
__device__ float4 g_xyzp[BQ * NQ];                  // packed xyz (orig order)
__device__ float4 g_sorted[BQ * NQ];                // cell-sorted xyz, .w = orig idx bits
__device__ float  g_featT[(size_t)BQ * NQ * CQ];    // features [B,N,C]
__device__ int    g_idx[BQ * SQ * NS];              // final sample indices
__device__ int    g_cellcnt[BQ * NCELL];            // histogram (re-zeroed each pass)
__device__ int    g_cellstart[BQ * (NCELL + 1)];    // exclusive prefix, [1000] = N
__device__ int    g_cellfill[BQ * NCELL];           // scatter cursors

__device__ __forceinline__ int cell_of(float v) {
    int c = (int)(v * 10.0f);
    return min(9, max(0, c));
}

// ---------------------------------------------------------------------------
// Prep 1: pack xyz + histogram cells
// ---------------------------------------------------------------------------
__global__ void pack_hist_kernel(const float* __restrict__ xyz) {
    int i = blockIdx.x * blockDim.x + threadIdx.x;
    if (i < BQ * NQ) {
        float x = xyz[3 * i + 0], y = xyz[3 * i + 1], z = xyz[3 * i + 2];
        g_xyzp[i] = make_float4(x, y, z, 0.0f);
        int b = i >> 14;
        int cell = (cell_of(z) * 10 + cell_of(y)) * 10 + cell_of(x);
        atomicAdd(&g_cellcnt[b * NCELL + cell], 1);
    }
}

// ---------------------------------------------------------------------------
// Prep 2: per-batch exclusive scan over 1000 cells; zero counts for next pass
// ---------------------------------------------------------------------------
__global__ void scan_kernel() {
    __shared__ int buf[1024];
    int b = blockIdx.x;
    int t = threadIdx.x;
    int v = (t < NCELL) ? g_cellcnt[b * NCELL + t] : 0;
    buf[t] = v;
    __syncthreads();
#pragma unroll
    for (int d = 1; d < 1024; d <<= 1) {
        int tv = (t >= d) ? buf[t - d] : 0;
        __syncthreads();
        buf[t] += tv;
        __syncthreads();
    }
    if (t < NCELL) {
        int excl = buf[t] - v;
        g_cellstart[b * (NCELL + 1) + t] = excl;
        g_cellfill[b * NCELL + t] = excl;
        g_cellcnt[b * NCELL + t] = 0;          // restore invariant for next replay
    }
    if (t == 0) g_cellstart[b * (NCELL + 1) + NCELL] = NQ;
}

// ---------------------------------------------------------------------------
// Prep 3: scatter points into cell-sorted order (orig idx in .w)
// ---------------------------------------------------------------------------
__global__ void scatter_kernel() {
    int i = blockIdx.x * blockDim.x + threadIdx.x;
    if (i < BQ * NQ) {
        int b = i >> 14, n = i & (NQ - 1);
        float4 p = g_xyzp[i];
        int cell = (cell_of(p.z) * 10 + cell_of(p.y)) * 10 + cell_of(p.x);
        int pos = atomicAdd(&g_cellfill[b * NCELL + cell], 1);
        g_sorted[b * NQ + pos] = make_float4(p.x, p.y, p.z, __int_as_float(n));
    }
}

// ---------------------------------------------------------------------------
// Prep 4: transpose features [B,C,N] -> [B,N,C]
// ---------------------------------------------------------------------------
__global__ void transpose_feat_kernel(const float* __restrict__ feat) {
    __shared__ float tile[32][33];
    int n0 = blockIdx.x * 32, c0 = blockIdx.y * 32, b = blockIdx.z;
    int tx = threadIdx.x, ty = threadIdx.y;
#pragma unroll
    for (int j = 0; j < 32; j += 8)
        tile[ty + j][tx] = feat[((size_t)b * CQ + (c0 + ty + j)) * NQ + (n0 + tx)];
    __syncthreads();
#pragma unroll
    for (int j = 0; j < 32; j += 8)
        g_featT[((size_t)b * NQ + (n0 + ty + j)) * CQ + (c0 + tx)] = tile[tx][ty + j];
}

// ---------------------------------------------------------------------------
// Ball query via grid: one warp per center, hits recorded in a 16384-bit
// smem bitmask (order-free), then first-32 extraction in ascending index order.
// ---------------------------------------------------------------------------
__global__ __launch_bounds__(WARPS_B * 32)
void ball_query_grid_kernel(const float* __restrict__ new_xyz,
                            float* __restrict__ out) {
    __shared__ unsigned mask[WARPS_B][NQ / 32];     // 2 KB per warp
    __shared__ int      sh_idx[WARPS_B][NS];

    const int warp = threadIdx.x >> 5;
    const int lane = threadIdx.x & 31;
    const int center = blockIdx.x * WARPS_B + warp;
    const int b = center / SQ;
    const int s = center % SQ;

    const float cx = new_xyz[3 * center + 0];
    const float cy = new_xyz[3 * center + 1];
    const float cz = new_xyz[3 * center + 2];
    const float r2 = (float)(0.1 * 0.1);

    // zero this warp's bitmask
#pragma unroll
    for (int i = lane; i < NQ / 32; i += 32) mask[warp][i] = 0;
    __syncwarp();

    // neighbor cell ranges with guard band against boundary rounding
    const int x0 = max(0, (int)floorf((cx - 0.1f) * 10.0f - 0.002f));
    const int x1 = min(9, (int)floorf((cx + 0.1f) * 10.0f + 0.002f));
    const int y0 = max(0, (int)floorf((cy - 0.1f) * 10.0f - 0.002f));
    const int y1 = min(9, (int)floorf((cy + 0.1f) * 10.0f + 0.002f));
    const int z0 = max(0, (int)floorf((cz - 0.1f) * 10.0f - 0.002f));
    const int z1 = min(9, (int)floorf((cz + 0.1f) * 10.0f + 0.002f));

    const float4* __restrict__ srt = g_sorted + (size_t)b * NQ;
    const int* __restrict__ cs = g_cellstart + b * (NCELL + 1);

    for (int zc = z0; zc <= z1; zc++) {
        for (int yc = y0; yc <= y1; yc++) {
            int rowbase = (zc * 10 + yc) * 10;
            int st = cs[rowbase + x0];
            int en = cs[rowbase + x1 + 1];         // x-contiguous cells
            for (int ibase = st; ibase < en; ibase += 32) {
                int i = ibase + lane;
                if (i < en) {
                    float4 p = srt[i];
                    float dx = __fadd_rn(cx, -p.x);
                    float dy = __fadd_rn(cy, -p.y);
                    float dz = __fadd_rn(cz, -p.z);
                    float d2 = __fadd_rn(__fadd_rn(__fmul_rn(dx, dx), __fmul_rn(dy, dy)),
                                         __fmul_rn(dz, dz));
                    if (d2 < r2) {
                        int oi = __float_as_int(p.w);
                        atomicOr(&mask[warp][oi >> 5], 1u << (oi & 31));
                    }
                }
            }
        }
    }
    __syncwarp();

    // extract first NS set bits in ascending index order
    int cnt = 0;
    for (int w0 = 0; w0 < NQ / 32 && cnt < NS; w0 += 32) {
        unsigned word = mask[warp][w0 + lane];
        int pc = __popc(word);
        int pre = pc;
#pragma unroll
        for (int d = 1; d < 32; d <<= 1) {
            int t = __shfl_up_sync(0xffffffffu, pre, d);
            if (lane >= d) pre += t;
        }
        int tot  = __shfl_sync(0xffffffffu, pre, 31);
        int pos  = cnt + pre - pc;                  // exclusive base for this lane
        if (word && pos < NS) {
            unsigned w = word;
            while (w && pos < NS) {
                int bpos = __ffs(w) - 1;
                sh_idx[warp][pos] = (w0 + lane) * 32 + bpos;
                w &= w - 1;
                pos++;
            }
        }
        cnt += tot;
    }
    __syncwarp();

    int myidx = (cnt == 0) ? 0 : sh_idx[warp][(lane < cnt) ? lane : 0];
    g_idx[center * NS + lane] = myidx;

    // grouped_xyz channels 0..2 (coalesced over lane=k)
    float4 p = g_xyzp[(size_t)b * NQ + myidx];
    const size_t chan_stride = (size_t)SQ * NS;
    float* ob = out + ((size_t)b * OUTC * SQ + s) * NS + lane;
    ob[0 * chan_stride] = __fadd_rn(p.x, -cx);
    ob[1 * chan_stride] = __fadd_rn(p.y, -cy);
    ob[2 * chan_stride] = __fadd_rn(p.z, -cz);
}

// ---------------------------------------------------------------------------
// Feature grouping: float4 gather + conflict-free float4 smem transpose
// ---------------------------------------------------------------------------
__global__ __launch_bounds__(128)
void group_feat_kernel(float* __restrict__ out) {
    __shared__ float4 sf4[NS][17];                  // pitch 17 float4 -> conflict-free
    __shared__ int    sidx[NS];

    const int center = blockIdx.x;
    const int b = center / SQ;
    const int s = center % SQ;
    const int tid = threadIdx.x;

    if (tid < NS) sidx[tid] = g_idx[center * NS + tid];
    __syncthreads();

    // gather: 8 rows x 16 float4 per step, 4 steps
    const float4* __restrict__ ft4 =
        (const float4*)(g_featT + (size_t)b * NQ * CQ);
    const int r  = tid >> 4;       // 0..7
    const int c4 = tid & 15;       // 0..15
#pragma unroll
    for (int r0 = 0; r0 < NS; r0 += 8)
        sf4[r0 + r][c4] = ft4[(size_t)sidx[r0 + r] * 16 + c4];
    __syncthreads();

    // write: lane = sample k (coalesced); each LDS.128 feeds 4 channel stores
    const int k = tid & 31;
    const int w = tid >> 5;        // 0..3
    const size_t chan_stride = (size_t)SQ * NS;
    float* ob = out + ((size_t)b * OUTC * SQ + s) * NS + k + 3 * chan_stride;
#pragma unroll
    for (int cc = w; cc < 16; cc += 4) {
        float4 v = sf4[k][cc];
        float* o = ob + (size_t)(4 * cc) * chan_stride;
        o[0 * chan_stride] = v.x;
        o[1 * chan_stride] = v.y;
        o[2 * chan_stride] = v.z;
        o[3 * chan_stride] = v.w;
    }
}

// ---------------------------------------------------------------------------
// Launch
// ---------------------------------------------------------------------------
extern "C" void kernel_launch(void* const* d_in, const int* in_sizes, int n_in,
                              void* d_out, int out_size) {
    const float* xyz     = (const float*)d_in[0];   // [B,N,3]
    const float* new_xyz = (const float*)d_in[1];   // [B,S,3]
    const float* feat    = (const float*)d_in[2];   // [B,C,N]
    float* out = (float*)d_out;                     // [B,67,S,NS]

    pack_hist_kernel<<<(BQ * NQ + 255) / 256, 256>>>(xyz);
    scan_kernel<<<BQ, 1024>>>();
    scatter_kernel<<<(BQ * NQ + 255) / 256, 256>>>();

    {
        dim3 grid(NQ / 32, CQ / 32, BQ);
        dim3 block(32, 8);
        transpose_feat_kernel<<<grid, block>>>(feat);
    }

    ball_query_grid_kernel<<<(BQ * SQ) / WARPS_B, WARPS_B * 32>>>(new_xyz, out);

    group_feat_kernel<<<BQ * SQ, 128>>>(out);
}